// round 1
// baseline (speedup 1.0000x reference)
#include <cuda_runtime.h>
#include <math.h>

// ---------------------------------------------------------------------------
// CoDAConv2d: out[b,o,h,w] = (patches . Wdyn[:,o]) / (||Wdyn[:,o]||_2 + eps)
// Wdyn[p,o] = sum_c in[b,c,h,w] * w_pred[p*16+o, c] + b_pred[p*16+o]
// patches p = c'*9 + dh*3 + dw  (SAME padding, 3x3)
//
// Rewritten:
//   act_o  = sum_c x_c * m[o,c] + z_o          (m = static 128-ch 3x3 conv)
//   norm_o = sqrt(x^T G_o x + 2 u_o^T x + s_o) + eps
// ---------------------------------------------------------------------------

#define B_  4
#define CI  8
#define CO  16
#define HH  112
#define WW  112
#define PATCH 72
#define EPS 1e-6f

#define CHUNK 16
#define NCHUNK (WW / CHUNK)             // 7
#define NTASK  (B_ * HH * NCHUNK)       // 3136
#define GRID   444                      // 148 SMs * 3 blocks

// Derived constant tables (filled per-launch by prep kernels)
__device__ float gF[PATCH * 128];   // gF[p*128 + t], t = o*8+c : w_pred[(p*16+o)*8+c]
__device__ float gZ[9 * 128];       // gZ[j*128 + t]            : b_pred[((c*9+j)*16)+o]
__device__ float gQ[10 * 128];      // k<8: G[o][c][k]; k=8: 2*u[o][c]; k=9: s[o]/8

// --- prep: fill gF, gZ --------------------------------------------------
__global__ void prepFZ_kernel(const float* __restrict__ w_pred,
                              const float* __restrict__ b_pred) {
    int p = blockIdx.x;          // 0..71
    int t = threadIdx.x;         // 0..127
    int o = t >> 3;
    int c = t & 7;
    gF[p * 128 + t] = w_pred[(p * 16 + o) * 8 + c];
    if (p < 9) gZ[p * 128 + t] = b_pred[(c * 9 + p) * 16 + o];
}

// --- prep: fill gQ (Gram matrix, u, s) per output channel o --------------
__global__ void prepQ_kernel(const float* __restrict__ w_pred,
                             const float* __restrict__ b_pred) {
    int o = blockIdx.x;          // 0..15
    int tid = threadIdx.x;       // 0..63
    int c = tid >> 3;
    int k = tid & 7;

    __shared__ float sw[PATCH][8];
    __shared__ float sb[PATCH];

    for (int idx = tid; idx < PATCH * 8; idx += 64) {
        int p = idx >> 3, cc = idx & 7;
        sw[p][cc] = w_pred[(p * 16 + o) * 8 + cc];
    }
    for (int idx = tid; idx < PATCH; idx += 64)
        sb[idx] = b_pred[idx * 16 + o];
    __syncthreads();

    // G[o][c][k]
    float acc = 0.f;
    #pragma unroll 8
    for (int p = 0; p < PATCH; p++) acc = fmaf(sw[p][c], sw[p][k], acc);
    gQ[k * 128 + o * 8 + c] = acc;

    if (k == 0) {
        float u = 0.f;
        #pragma unroll 8
        for (int p = 0; p < PATCH; p++) u = fmaf(sw[p][c], sb[p], u);
        gQ[8 * 128 + o * 8 + c] = 2.0f * u;
    }
    if (tid == 0) {
        float s = 0.f;
        #pragma unroll 8
        for (int p = 0; p < PATCH; p++) s = fmaf(sb[p], sb[p], s);
        s *= 0.125f;
        #pragma unroll
        for (int cc = 0; cc < 8; cc++) gQ[9 * 128 + o * 8 + cc] = s;
    }
}

// --- main kernel ----------------------------------------------------------
__global__ __launch_bounds__(128, 3)
void coda_main_kernel(const float* __restrict__ in, float* __restrict__ out) {
    const int t = threadIdx.x;          // 0..127  -> (o, c)
    const int o = t >> 3;
    const int c = t & 7;

    // Per-thread constant tables in registers (all indices compile-time)
    float Freg[PATCH];
    #pragma unroll
    for (int p = 0; p < PATCH; p++) Freg[p] = gF[p * 128 + t];
    float Zreg[9];
    #pragma unroll
    for (int j = 0; j < 9; j++) Zreg[j] = gZ[j * 128 + t];
    float Qreg[10];
    #pragma unroll
    for (int k = 0; k < 10; k++) Qreg[k] = gQ[k * 128 + t];

    // channel-last input tile: [row 0..2][col 0..CHUNK+1][ch 0..7]
    __shared__ float tile[3][CHUNK + 2][8];

    for (int task = blockIdx.x; task < NTASK; task += gridDim.x) {
        const int rowid = task / NCHUNK;            // 0..447
        const int cw    = (task % NCHUNK) * CHUNK;  // 0,16,...,96
        const int b     = rowid / HH;
        const int h     = rowid % HH;

        __syncthreads();   // previous task's readers done before overwrite
        // cooperative tile load: 3 * (CHUNK+2) * 8 = 432 floats
        for (int idx = t; idx < 3 * (CHUNK + 2) * 8; idx += 128) {
            int ch   = idx & 7;
            int rest = idx >> 3;
            int col  = rest % (CHUNK + 2);
            int r    = rest / (CHUNK + 2);
            int ir   = h - 1 + r;
            int ic   = cw - 1 + col;
            float v = 0.f;
            if ((unsigned)ir < (unsigned)HH && (unsigned)ic < (unsigned)WW)
                v = in[((b * CI + ch) * HH + ir) * WW + ic];
            tile[r][col][ch] = v;
        }
        __syncthreads();

        #pragma unroll 1
        for (int wl = 0; wl < CHUNK; wl++) {
            float m0 = 0.f, m1 = 0.f, m2 = 0.f, m3 = 0.f, z = 0.f;
            float x0, x1, x2, x3, x4, x5, x6, x7, xc;

            #pragma unroll
            for (int dh = 0; dh < 3; dh++) {
                #pragma unroll
                for (int dw = 0; dw < 3; dw++) {
                    const int j = dh * 3 + dw;
                    const float* pv = &tile[dh][wl + dw][0];
                    const float4 a  = *(const float4*)pv;
                    const float4 b4 = *(const float4*)(pv + 4);
                    const float vc  = pv[c];   // this thread's own channel

                    m0 = fmaf(a.x,  Freg[ 0 + j], m0);
                    m1 = fmaf(a.y,  Freg[ 9 + j], m1);
                    m2 = fmaf(a.z,  Freg[18 + j], m2);
                    m3 = fmaf(a.w,  Freg[27 + j], m3);
                    m0 = fmaf(b4.x, Freg[36 + j], m0);
                    m1 = fmaf(b4.y, Freg[45 + j], m1);
                    m2 = fmaf(b4.z, Freg[54 + j], m2);
                    m3 = fmaf(b4.w, Freg[63 + j], m3);
                    z  = fmaf(vc, Zreg[j], z);

                    if (dh == 1 && dw == 1) {
                        x0 = a.x;  x1 = a.y;  x2 = a.z;  x3 = a.w;
                        x4 = b4.x; x5 = b4.y; x6 = b4.z; x7 = b4.w;
                        xc = vc;
                    }
                }
            }
            const float m = (m0 + m1) + (m2 + m3);

            // quadratic form partial: x_c * (G_row . x + 2u_c) + s/8
            float qd = Qreg[8];
            qd = fmaf(x0, Qreg[0], qd); qd = fmaf(x1, Qreg[1], qd);
            qd = fmaf(x2, Qreg[2], qd); qd = fmaf(x3, Qreg[3], qd);
            qd = fmaf(x4, Qreg[4], qd); qd = fmaf(x5, Qreg[5], qd);
            qd = fmaf(x6, Qreg[6], qd); qd = fmaf(x7, Qreg[7], qd);
            float qv = fmaf(xc, qd, Qreg[9]);
            float av = fmaf(xc, m, z);

            // reduce over the 8 c-lanes (lane bits 0..2)
            #pragma unroll
            for (int s = 1; s < 8; s <<= 1) {
                av += __shfl_xor_sync(0xffffffffu, av, s);
                qv += __shfl_xor_sync(0xffffffffu, qv, s);
            }

            if (c == 0) {
                qv = fmaxf(qv, 0.f);
                out[((b * CO + o) * HH + h) * WW + (cw + wl)] =
                    av / (sqrtf(qv) + EPS);
            }
        }
    }
}

// ---------------------------------------------------------------------------
extern "C" void kernel_launch(void* const* d_in, const int* in_sizes, int n_in,
                              void* d_out, int out_size) {
    const float* in_tensor = (const float*)d_in[0];
    const float* w_pred    = (const float*)d_in[1];
    const float* b_pred    = (const float*)d_in[2];
    float* out = (float*)d_out;

    prepFZ_kernel<<<PATCH, 128>>>(w_pred, b_pred);
    prepQ_kernel<<<CO, 64>>>(w_pred, b_pred);
    coda_main_kernel<<<GRID, 128>>>(in_tensor, out);
}

// round 2
// speedup vs baseline: 1.3267x; 1.3267x over previous
#include <cuda_runtime.h>
#include <math.h>

// ---------------------------------------------------------------------------
// CoDAConv2d: out[b,o,h,w] = (patches . Wdyn[:,o]) / (||Wdyn[:,o]||_2 + eps)
// Rewritten:
//   act_o  = sum_c x_c * (A_o^T nb)_c + nb.b_o
//   norm_o = sqrt(x^T G_o x + 2 u_o^T x + s_o) + eps   (G_o = A_o^T A_o)
// Thread t = (o, c): 16 output channels x 8 input channels = 128 threads.
// 4-pixel register blocking, prefetched tiles, atomic task scheduler.
// ---------------------------------------------------------------------------

#define B_  4
#define CI  8
#define CO  16
#define HH  112
#define WW  112
#define PATCH 72
#define EPS 1e-6f

#define CHUNK 16
#define COLS  (CHUNK + 2)               // 18
#define TILE_ELEMS (3 * COLS * 8)       // 432
#define NCHUNK (WW / CHUNK)             // 7
#define NTASK  (B_ * HH * NCHUNK)       // 3136
#define GRID   444                      // 148 SMs * 3 blocks

// Derived constant tables + task counter
__device__ float gF[PATCH * 128];   // gF[p*128+t], t=o*8+c : w_pred[(p*16+o)*8+c]
__device__ float gZ[9 * 128];       // gZ[j*128+t]          : b_pred[(c*9+j)*16+o]
__device__ float gQ[10 * 128];      // k<8: G[o][c][k]; k=8: 2u[o][c]; k=9: s[o]/8
__device__ int   gCtr;

// --- merged prep kernel ----------------------------------------------------
__global__ void coda_prep_kernel(const float* __restrict__ w_pred,
                                 const float* __restrict__ b_pred) {
    const int bx  = blockIdx.x;
    const int tid = threadIdx.x;

    if (bx == 0 && tid == 0) gCtr = 0;

    if (bx < PATCH) {
        // FZ part: one block per patch index p
        const int p = bx;
        const int o = tid >> 3;
        const int c = tid & 7;
        gF[p * 128 + tid] = w_pred[(p * 16 + o) * 8 + c];
        if (p < 9) gZ[p * 128 + tid] = b_pred[(c * 9 + p) * 16 + o];
        return;
    }

    // Q part: one block per output channel o
    const int o = bx - PATCH;
    __shared__ float sw[PATCH][8];
    __shared__ float sb[PATCH];

    for (int idx = tid; idx < PATCH * 8; idx += 128) {
        int p = idx >> 3, cc = idx & 7;
        sw[p][cc] = w_pred[(p * 16 + o) * 8 + cc];
    }
    for (int idx = tid; idx < PATCH; idx += 128)
        sb[idx] = b_pred[idx * 16 + o];
    __syncthreads();

    if (tid < 64) {
        const int c = tid >> 3;
        const int k = tid & 7;
        float acc = 0.f;
        #pragma unroll 8
        for (int p = 0; p < PATCH; p++) acc = fmaf(sw[p][c], sw[p][k], acc);
        gQ[k * 128 + o * 8 + c] = acc;

        if (k == 0) {
            float u = 0.f;
            #pragma unroll 8
            for (int p = 0; p < PATCH; p++) u = fmaf(sw[p][c], sb[p], u);
            gQ[8 * 128 + o * 8 + c] = 2.0f * u;
        }
        if (tid == 0) {
            float s = 0.f;
            #pragma unroll 8
            for (int p = 0; p < PATCH; p++) s = fmaf(sb[p], sb[p], s);
            s *= 0.125f;
            #pragma unroll
            for (int cc = 0; cc < 8; cc++) gQ[9 * 128 + o * 8 + cc] = s;
        }
    }
}

// --- prefetch loader: task tile -> 4 registers per thread -------------------
__device__ __forceinline__ void load_task(const float* __restrict__ in,
                                          int task, int t, float pre[4]) {
    const int rowid = task / NCHUNK;
    const int cw    = (task % NCHUNK) * CHUNK;
    const int b     = rowid / HH;
    const int h     = rowid % HH;
    #pragma unroll
    for (int k = 0; k < 4; k++) {
        int idx = t + k * 128;
        float v = 0.f;
        if (idx < TILE_ELEMS) {
            int ch   = idx & 7;
            int rest = idx >> 3;
            int col  = rest % COLS;
            int r    = rest / COLS;
            int ir   = h - 1 + r;
            int ic   = cw - 1 + col;
            if ((unsigned)ir < (unsigned)HH && (unsigned)ic < (unsigned)WW)
                v = __ldg(&in[((b * CI + ch) * HH + ir) * WW + ic]);
        }
        pre[k] = v;
    }
}

// --- main kernel -------------------------------------------------------------
__global__ __launch_bounds__(128, 3)
void coda_main_kernel(const float* __restrict__ in, float* __restrict__ out) {
    const int t = threadIdx.x;          // (o, c)
    const int o = t >> 3;
    const int c = t & 7;

    float Freg[PATCH];
    #pragma unroll
    for (int p = 0; p < PATCH; p++) Freg[p] = gF[p * 128 + t];
    float Zreg[9];
    #pragma unroll
    for (int j = 0; j < 9; j++) Zreg[j] = gZ[j * 128 + t];
    float Qreg[10];
    #pragma unroll
    for (int k = 0; k < 10; k++) Qreg[k] = gQ[k * 128 + t];

    __shared__ float tile[3][COLS][8];
    __shared__ int   sTask;

    float pre[4];

    if (t == 0) sTask = atomicAdd(&gCtr, 1);
    __syncthreads();
    int task = sTask;
    if (task >= NTASK) return;
    load_task(in, task, t, pre);

    while (true) {
        // publish prefetched tile
        #pragma unroll
        for (int k = 0; k < 4; k++) {
            int idx = t + k * 128;
            if (idx < TILE_ELEMS) ((float*)tile)[idx] = pre[k];
        }
        if (t == 0) sTask = atomicAdd(&gCtr, 1);
        __syncthreads();
        const int nxt = sTask;
        if (nxt < NTASK) load_task(in, nxt, t, pre);   // overlaps compute

        const int rowid = task / NCHUNK;
        const int cw    = (task % NCHUNK) * CHUNK;
        const int b     = rowid / HH;
        const int h     = rowid % HH;
        float* orow = &out[((b * CO + o) * HH + h) * WW + cw];

        #pragma unroll 1
        for (int wlb = 0; wlb < CHUNK; wlb += 4) {
            float ma[4], mb[4], z[4], xc[4];
            #pragma unroll
            for (int px = 0; px < 4; px++) { ma[px] = 0.f; mb[px] = 0.f; z[px] = 0.f; }

            #pragma unroll
            for (int dh = 0; dh < 3; dh++) {
                #pragma unroll
                for (int k = 0; k < 6; k++) {
                    const float* pv = &tile[dh][wlb + k][0];
                    const float4 A = *(const float4*)pv;
                    const float4 Bv = *(const float4*)(pv + 4);
                    const float  vc = pv[c];
                    const int pxlo = (k - 2 > 0) ? (k - 2) : 0;
                    const int pxhi = (k < 3) ? k : 3;
                    #pragma unroll
                    for (int px = pxlo; px <= pxhi; px++) {
                        const int j = dh * 3 + (k - px);
                        ma[px] = fmaf(A.x,  Freg[ 0 + j], ma[px]);
                        mb[px] = fmaf(A.y,  Freg[ 9 + j], mb[px]);
                        ma[px] = fmaf(A.z,  Freg[18 + j], ma[px]);
                        mb[px] = fmaf(A.w,  Freg[27 + j], mb[px]);
                        ma[px] = fmaf(Bv.x, Freg[36 + j], ma[px]);
                        mb[px] = fmaf(Bv.y, Freg[45 + j], mb[px]);
                        ma[px] = fmaf(Bv.z, Freg[54 + j], ma[px]);
                        mb[px] = fmaf(Bv.w, Freg[63 + j], mb[px]);
                        z[px]  = fmaf(vc, Zreg[j], z[px]);
                    }
                    if (dh == 1 && k >= 1 && k <= 4) xc[k - 1] = vc;
                }
            }

            float4 outv;
            float res[4];
            #pragma unroll
            for (int px = 0; px < 4; px++) {
                float av = fmaf(xc[px], ma[px] + mb[px], z[px]);

                // quadratic form: reload the center column for this pixel
                const float* pv = &tile[1][wlb + px + 1][0];
                const float4 A = *(const float4*)pv;
                const float4 Bv = *(const float4*)(pv + 4);
                float qd = Qreg[8];
                qd = fmaf(A.x,  Qreg[0], qd); qd = fmaf(A.y,  Qreg[1], qd);
                qd = fmaf(A.z,  Qreg[2], qd); qd = fmaf(A.w,  Qreg[3], qd);
                qd = fmaf(Bv.x, Qreg[4], qd); qd = fmaf(Bv.y, Qreg[5], qd);
                qd = fmaf(Bv.z, Qreg[6], qd); qd = fmaf(Bv.w, Qreg[7], qd);
                float qv = fmaf(xc[px], qd, Qreg[9]);

                #pragma unroll
                for (int s = 1; s < 8; s <<= 1) {
                    av += __shfl_xor_sync(0xffffffffu, av, s);
                    qv += __shfl_xor_sync(0xffffffffu, qv, s);
                }
                qv = fmaxf(qv, 0.f);
                res[px] = av / (sqrtf(qv) + EPS);
            }
            outv.x = res[0]; outv.y = res[1]; outv.z = res[2]; outv.w = res[3];
            if (c == 0) *(float4*)&orow[wlb] = outv;
        }

        __syncthreads();   // tile readers done before next overwrite
        if (nxt >= NTASK) return;
        task = nxt;
    }
}

// ---------------------------------------------------------------------------
extern "C" void kernel_launch(void* const* d_in, const int* in_sizes, int n_in,
                              void* d_out, int out_size) {
    const float* in_tensor = (const float*)d_in[0];
    const float* w_pred    = (const float*)d_in[1];
    const float* b_pred    = (const float*)d_in[2];
    float* out = (float*)d_out;

    coda_prep_kernel<<<PATCH + CO, 128>>>(w_pred, b_pred);
    coda_main_kernel<<<GRID, 128>>>(in_tensor, out);
}

// round 3
// speedup vs baseline: 1.3940x; 1.0508x over previous
#include <cuda_runtime.h>
#include <math.h>

// ---------------------------------------------------------------------------
// CoDAConv2d rewritten:
//   act_o  = sum_c x_c * (A_o^T nb)_c + nb.b_o
//   norm_o = sqrt(x^T G_o x + 2 u_o^T x + s_o) + eps
// Thread t=(o,c). f32x2 packed FMA over channel pairs; 4px register blocking;
// 8-value/8-lane butterfly reduction; atomic task scheduler + prefetch.
// ---------------------------------------------------------------------------

#define B_  4
#define CI  8
#define CO  16
#define HH  112
#define WW  112
#define PATCH 72
#define EPS 1e-6f

#define CHUNK 16
#define COLS  (CHUNK + 2)               // 18
#define TILE_ELEMS (3 * COLS * 8)       // 432
#define NCHUNK (WW / CHUNK)             // 7
#define NTASK  (B_ * HH * NCHUNK)       // 3136
#define GRID   444

typedef unsigned long long ull;

// packed-pair tables
__device__ ull   gF2[36 * 128];   // [i*9+j][t] : (F[c'=2i], F[c'=2i+1]) at tap j
__device__ float gZ[9 * 128];     // bias-conv taps
__device__ ull   gQ2[4 * 128];    // (G[c][2k],G[c][2k+1])
__device__ float gU[128];         // 2*u[o][c]
__device__ float gS[128];         // s[o]/8
__device__ int   gCtr;

// --- f32x2 helpers -----------------------------------------------------------
__device__ __forceinline__ ull ffma2(ull a, ull b, ull c) {
    ull d; asm("fma.rn.f32x2 %0, %1, %2, %3;" : "=l"(d) : "l"(a), "l"(b), "l"(c));
    return d;
}
__device__ __forceinline__ ull fadd2(ull a, ull b) {
    ull d; asm("add.rn.f32x2 %0, %1, %2;" : "=l"(d) : "l"(a), "l"(b));
    return d;
}
__device__ __forceinline__ ull pack2(float lo, float hi) {
    ull d; asm("mov.b64 %0, {%1, %2};" : "=l"(d) : "f"(lo), "f"(hi));
    return d;
}
__device__ __forceinline__ float hsum2(ull a) {
    float lo, hi; asm("mov.b64 {%0, %1}, %2;" : "=f"(lo), "=f"(hi) : "l"(a));
    return lo + hi;
}

// --- prep kernel ---------------------------------------------------------------
__global__ void coda_prep_kernel(const float* __restrict__ w_pred,
                                 const float* __restrict__ b_pred) {
    const int bx  = blockIdx.x;
    const int tid = threadIdx.x;
    if (bx == 0 && tid == 0) gCtr = 0;

    if (bx < 36) {
        const int i = bx / 9, j = bx % 9;
        const int o = tid >> 3, c = tid & 7;
        float lo = w_pred[(((2 * i)     * 9 + j) * 16 + o) * 8 + c];
        float hi = w_pred[(((2 * i + 1) * 9 + j) * 16 + o) * 8 + c];
        gF2[bx * 128 + tid] = pack2(lo, hi);
        if (bx < 9) gZ[bx * 128 + tid] = b_pred[(c * 9 + bx) * 16 + o];
        return;
    }

    // Gram part: one block per output channel o
    const int o = bx - 36;
    __shared__ float sw[PATCH][8];
    __shared__ float sb[PATCH];
    __shared__ float sG[8][8];

    for (int idx = tid; idx < PATCH * 8; idx += 128) {
        int p = idx >> 3, cc = idx & 7;
        sw[p][cc] = w_pred[(p * 16 + o) * 8 + cc];
    }
    for (int idx = tid; idx < PATCH; idx += 128)
        sb[idx] = b_pred[idx * 16 + o];
    __syncthreads();

    if (tid < 64) {
        const int c = tid >> 3, k = tid & 7;
        float acc = 0.f;
        #pragma unroll 8
        for (int p = 0; p < PATCH; p++) acc = fmaf(sw[p][c], sw[p][k], acc);
        sG[c][k] = acc;

        if (k == 0) {
            float u = 0.f;
            #pragma unroll 8
            for (int p = 0; p < PATCH; p++) u = fmaf(sw[p][c], sb[p], u);
            gU[o * 8 + c] = 2.0f * u;
        }
        if (tid == 0) {
            float s = 0.f;
            #pragma unroll 8
            for (int p = 0; p < PATCH; p++) s = fmaf(sb[p], sb[p], s);
            s *= 0.125f;
            #pragma unroll
            for (int cc = 0; cc < 8; cc++) gS[o * 8 + cc] = s;
        }
    }
    __syncthreads();
    if (tid < 8) {
        #pragma unroll
        for (int kk = 0; kk < 4; kk++)
            gQ2[kk * 128 + o * 8 + tid] = pack2(sG[tid][2 * kk], sG[tid][2 * kk + 1]);
    }
}

// --- prefetch loader --------------------------------------------------------
__device__ __forceinline__ void load_task(const float* __restrict__ in,
                                          int task, int t, float pre[4]) {
    const int rowid = task / NCHUNK;
    const int cw    = (task % NCHUNK) * CHUNK;
    const int b     = rowid / HH;
    const int h     = rowid % HH;
    #pragma unroll
    for (int k = 0; k < 4; k++) {
        int idx = t + k * 128;
        float v = 0.f;
        if (idx < TILE_ELEMS) {
            int ch   = idx & 7;
            int rest = idx >> 3;
            int col  = rest % COLS;
            int r    = rest / COLS;
            int ir   = h - 1 + r;
            int ic   = cw - 1 + col;
            if ((unsigned)ir < (unsigned)HH && (unsigned)ic < (unsigned)WW)
                v = __ldg(&in[((b * CI + ch) * HH + ir) * WW + ic]);
        }
        pre[k] = v;
    }
}

// --- main kernel ----------------------------------------------------------------
__global__ __launch_bounds__(128, 3)
void coda_main_kernel(const float* __restrict__ in, float* __restrict__ out) {
    const int t = threadIdx.x;
    const int o = t >> 3;
    const int c = t & 7;

    ull Fp[36];
    #pragma unroll
    for (int p = 0; p < 36; p++) Fp[p] = gF2[p * 128 + t];
    float Zreg[9];
    #pragma unroll
    for (int j = 0; j < 9; j++) Zreg[j] = gZ[j * 128 + t];
    ull Qp[4];
    #pragma unroll
    for (int k = 0; k < 4; k++) Qp[k] = gQ2[k * 128 + t];
    const ull   qinit = pack2(gU[t], 0.f);
    const float Qs    = gS[t];

    __shared__ float tile[3][COLS][8];
    __shared__ int   sTask;

    float pre[4];

    if (t == 0) sTask = atomicAdd(&gCtr, 1);
    __syncthreads();
    int task = sTask;
    if (task >= NTASK) return;
    load_task(in, task, t, pre);

    while (true) {
        #pragma unroll
        for (int k = 0; k < 4; k++) {
            int idx = t + k * 128;
            if (idx < TILE_ELEMS) ((float*)tile)[idx] = pre[k];
        }
        if (t == 0) sTask = atomicAdd(&gCtr, 1);
        __syncthreads();
        const int nxt = sTask;
        if (nxt < NTASK) load_task(in, nxt, t, pre);

        const int rowid = task / NCHUNK;
        const int cw    = (task % NCHUNK) * CHUNK;
        const int b     = rowid / HH;
        const int h     = rowid % HH;
        float* orow = &out[((b * CO + o) * HH + h) * WW + cw];

        #pragma unroll 1
        for (int wlb = 0; wlb < CHUNK; wlb += 4) {
            ull  m0[4], m1[4], m2[4], m3[4];
            float z[4], xc[4];
            ull  qp[4];
            #pragma unroll
            for (int px = 0; px < 4; px++) {
                m0[px] = 0ull; m1[px] = 0ull; m2[px] = 0ull; m3[px] = 0ull;
                z[px] = 0.f;
            }

            #pragma unroll
            for (int dh = 0; dh < 3; dh++) {
                #pragma unroll
                for (int k = 0; k < 6; k++) {
                    const float* pv = &tile[dh][wlb + k][0];
                    const ulonglong2 VA = *(const ulonglong2*)pv;       // (c0,c1),(c2,c3)
                    const ulonglong2 VB = *((const ulonglong2*)pv + 1); // (c4,c5),(c6,c7)
                    const float vc = pv[c];

                    const int pxlo = (k - 2 > 0) ? (k - 2) : 0;
                    const int pxhi = (k < 3) ? k : 3;
                    #pragma unroll
                    for (int px = pxlo; px <= pxhi; px++) {
                        const int j = dh * 3 + (k - px);
                        m0[px] = ffma2(VA.x, Fp[ 0 + j], m0[px]);
                        m1[px] = ffma2(VA.y, Fp[ 9 + j], m1[px]);
                        m2[px] = ffma2(VB.x, Fp[18 + j], m2[px]);
                        m3[px] = ffma2(VB.y, Fp[27 + j], m3[px]);
                        z[px]  = fmaf(vc, Zreg[j], z[px]);
                    }
                    if (dh == 1 && k >= 1 && k <= 4) {
                        const int px = k - 1;
                        xc[px] = vc;
                        ull qa = ffma2(VA.x, Qp[0], qinit);
                        qa = ffma2(VB.x, Qp[2], qa);
                        ull qb = ffma2(VA.y, Qp[1], 0ull);
                        qb = ffma2(VB.y, Qp[3], qb);
                        qp[px] = fadd2(qa, qb);
                    }
                }
            }

            // per-pixel scalars
            float r[8];
            #pragma unroll
            for (int px = 0; px < 4; px++) {
                float m = hsum2(fadd2(fadd2(m0[px], m1[px]), fadd2(m2[px], m3[px])));
                r[px]     = fmaf(xc[px], m, z[px]);            // av partial
                r[px + 4] = fmaf(xc[px], hsum2(qp[px]), Qs);   // qv partial
            }

            // 8-value / 8-lane butterfly reduction: lane c ends with sum of r[c]
            const bool h0 = c & 1, h1 = c & 2, h2 = c & 4;
            float s4[4];
            #pragma unroll
            for (int i = 0; i < 4; i++) {
                float give = h0 ? r[2 * i] : r[2 * i + 1];
                float got  = __shfl_xor_sync(0xffffffffu, give, 1);
                s4[i] = (h0 ? r[2 * i + 1] : r[2 * i]) + got;
            }
            float u2[2];
            #pragma unroll
            for (int i = 0; i < 2; i++) {
                float give = h1 ? s4[2 * i] : s4[2 * i + 1];
                float got  = __shfl_xor_sync(0xffffffffu, give, 2);
                u2[i] = (h1 ? s4[2 * i + 1] : s4[2 * i]) + got;
            }
            {
                float give = h2 ? u2[0] : u2[1];
                float got  = __shfl_xor_sync(0xffffffffu, give, 4);
                float tot  = (h2 ? u2[1] : u2[0]) + got;     // lane c: sum of r[c]
                float other = __shfl_xor_sync(0xffffffffu, tot, 4);
                if (c < 4) {
                    float qv = fmaxf(other, 0.f);
                    orow[wlb + c] = tot / (sqrtf(qv) + EPS);
                }
            }
        }

        __syncthreads();
        if (nxt >= NTASK) return;
        task = nxt;
    }
}

// ---------------------------------------------------------------------------
extern "C" void kernel_launch(void* const* d_in, const int* in_sizes, int n_in,
                              void* d_out, int out_size) {
    const float* in_tensor = (const float*)d_in[0];
    const float* w_pred    = (const float*)d_in[1];
    const float* b_pred    = (const float*)d_in[2];
    float* out = (float*)d_out;

    coda_prep_kernel<<<36 + CO, 128>>>(w_pred, b_pred);
    coda_main_kernel<<<GRID, 128>>>(in_tensor, out);
}